// round 15
// baseline (speedup 1.0000x reference)
#include <cuda_runtime.h>
#include <cuda.h>
#include <cuda_bf16.h>
#include <math.h>
#include <cstdint>

#define MAXN 50000
#define INCH 128
#define HID  256
#define CAP  64

#if defined(__CUDA_ARCH__) && (defined(__CUDA_ARCH_FEAT_SM103_ALL) || defined(__CUDA_ARCH_FEAT_SM100_ALL))
#define HAS_TCGEN05 1
#else
#define HAS_TCGEN05 0
#endif

// ---------------------------------------------------------------------------
// PTX helpers (guarded: only expanded in the sm_103a pass)
// ---------------------------------------------------------------------------
#if HAS_TCGEN05

__device__ __forceinline__ uint32_t smem_to_u32(const void* smem_ptr) {
    uint32_t addr;
    asm("{ .reg .u64 tmp; cvta.to.shared.u64 tmp, %1; cvt.u32.u64 %0, tmp; }"
        : "=r"(addr) : "l"(smem_ptr));
    return addr;
}

#define TCGEN05_ALLOC(smem_result_addr, nCols) \
    asm volatile( \
        "tcgen05.alloc.cta_group::1.sync.aligned.shared::cta.b32 [%0], %1;" \
        :: "r"((uint32_t)(smem_result_addr)), "r"((uint32_t)(nCols)) \
        : "memory")

#define TCGEN05_DEALLOC(tmem_addr, nCols) \
    asm volatile( \
        "tcgen05.dealloc.cta_group::1.sync.aligned.b32 %0, %1;" \
        :: "r"(tmem_addr), "r"((uint32_t)(nCols)))

#define TCGEN05_RELINQUISH_ALLOC_PERMIT() \
    asm volatile("tcgen05.relinquish_alloc_permit.cta_group::1.sync.aligned;")

#define TCGEN05_COMMIT(mbar_smem_addr) \
    asm volatile( \
        "tcgen05.commit.cta_group::1.mbarrier::arrive::one.shared::cluster.b64 [%0];" \
        :: "r"((uint32_t)(mbar_smem_addr)) \
        : "memory")

#define TCGEN05_WAIT_LD() \
    asm volatile("tcgen05.wait::ld.sync.aligned;" ::: "memory")

#define TCGEN05_WAIT_ST() \
    asm volatile("tcgen05.wait::st.sync.aligned;" ::: "memory")

#define TCGEN05_FENCE_BEFORE() \
    asm volatile("tcgen05.fence::before_thread_sync;" ::: "memory")

#define TCGEN05_FENCE_AFTER() \
    asm volatile("tcgen05.fence::after_thread_sync;" ::: "memory")

#define FENCE_PROXY_ASYNC_SHARED_CTA() \
    asm volatile("fence.proxy.async.shared::cta;" ::: "memory")

#define MBARRIER_INIT(mbar_smem_addr, count) \
    asm volatile( \
        "mbarrier.init.shared.b64 [%0], %1;" \
        :: "r"((uint32_t)(mbar_smem_addr)), "r"((uint32_t)(count)) \
        : "memory")

#define MBARRIER_EXPECT_TX(mbar_smem_addr, tx_bytes) \
    asm volatile( \
        "mbarrier.arrive.expect_tx.shared.b64 _, [%0], %1;" \
        :: "r"((uint32_t)(mbar_smem_addr)), "r"((uint32_t)(tx_bytes)) \
        : "memory")

#define MBARRIER_WAIT_PARITY(mbar_smem_addr, phase_parity) do { \
    uint32_t _mbar = (uint32_t)(mbar_smem_addr); \
    uint32_t _parity = (uint32_t)(phase_parity); \
    uint32_t _done; \
    asm volatile( \
        "{\n\t" \
        ".reg .pred p;\n\t" \
        "mbarrier.try_wait.parity.acquire.cta.shared::cta.b64 p, [%1], %2;\n\t" \
        "selp.b32 %0, 1, 0, p;\n\t" \
        "}" \
        : "=r"(_done) : "r"(_mbar), "r"(_parity) : "memory"); \
    if (!_done) { \
        asm volatile( \
            "{\n\t" \
            ".reg .pred P1;\n\t" \
            "WAIT_LOOP_%=:\n\t" \
            "mbarrier.try_wait.parity.acquire.cta.shared::cta.b64 P1, [%0], %1, 0x989680;\n\t" \
            "@P1 bra.uni WAIT_DONE_%=;\n\t" \
            "bra.uni WAIT_LOOP_%=;\n\t" \
            "WAIT_DONE_%=:\n\t" \
            "}" \
            :: "r"(_mbar), "r"(_parity) : "memory"); \
    } \
} while(0)

#define TMA_LOAD_2D(smem_addr, map_ptr, cx, cy, mbar) \
    asm volatile( \
        "cp.async.bulk.tensor.2d.shared::cta.global.tile.mbarrier::complete_tx::bytes " \
        "[%0], [%1, {%2, %3}], [%4];" \
        :: "r"((uint32_t)(smem_addr)), "l"(map_ptr), "r"((int)(cx)), "r"((int)(cy)), \
           "r"((uint32_t)(mbar)) \
        : "memory")

#define TCGEN05_LD_32X32B_X32(r, tmem_addr) \
    asm volatile( \
        "tcgen05.ld.sync.aligned.32x32b.x32.b32 " \
        "{%0, %1, %2, %3, %4, %5, %6, %7, " \
        " %8, %9, %10, %11, %12, %13, %14, %15, " \
        " %16, %17, %18, %19, %20, %21, %22, %23, " \
        " %24, %25, %26, %27, %28, %29, %30, %31}, [%32];" \
        : "=r"((r)[0]),  "=r"((r)[1]),  "=r"((r)[2]),  "=r"((r)[3]), \
          "=r"((r)[4]),  "=r"((r)[5]),  "=r"((r)[6]),  "=r"((r)[7]), \
          "=r"((r)[8]),  "=r"((r)[9]),  "=r"((r)[10]), "=r"((r)[11]), \
          "=r"((r)[12]), "=r"((r)[13]), "=r"((r)[14]), "=r"((r)[15]), \
          "=r"((r)[16]), "=r"((r)[17]), "=r"((r)[18]), "=r"((r)[19]), \
          "=r"((r)[20]), "=r"((r)[21]), "=r"((r)[22]), "=r"((r)[23]), \
          "=r"((r)[24]), "=r"((r)[25]), "=r"((r)[26]), "=r"((r)[27]), \
          "=r"((r)[28]), "=r"((r)[29]), "=r"((r)[30]), "=r"((r)[31]) \
        : "r"(tmem_addr))

#define TCGEN05_ST_32X32B_X32(tmem_addr, r) \
    asm volatile( \
        "tcgen05.st.sync.aligned.32x32b.x32.b32 [%0], " \
        "{%1, %2, %3, %4, %5, %6, %7, %8, " \
        " %9, %10, %11, %12, %13, %14, %15, %16, " \
        " %17, %18, %19, %20, %21, %22, %23, %24, " \
        " %25, %26, %27, %28, %29, %30, %31, %32};" \
        :: "r"(tmem_addr), \
           "r"((r)[0]),  "r"((r)[1]),  "r"((r)[2]),  "r"((r)[3]), \
           "r"((r)[4]),  "r"((r)[5]),  "r"((r)[6]),  "r"((r)[7]), \
           "r"((r)[8]),  "r"((r)[9]),  "r"((r)[10]), "r"((r)[11]), \
           "r"((r)[12]), "r"((r)[13]), "r"((r)[14]), "r"((r)[15]), \
           "r"((r)[16]), "r"((r)[17]), "r"((r)[18]), "r"((r)[19]), \
           "r"((r)[20]), "r"((r)[21]), "r"((r)[22]), "r"((r)[23]), \
           "r"((r)[24]), "r"((r)[25]), "r"((r)[26]), "r"((r)[27]), \
           "r"((r)[28]), "r"((r)[29]), "r"((r)[30]), "r"((r)[31]) \
        : "memory")

static constexpr uint64_t SMEM_DESC_BASE_SW128 =
    (uint64_t(2)  << 61)
    | (uint64_t(1) << 46)
    | (uint64_t(64) << 32)
    | (uint64_t(1) << 16);

#define MAKE_SMEM_DESC(base_addr) \
    (SMEM_DESC_BASE_SW128 | ((uint64_t)((base_addr) >> 4) & 0x3FFF))

__device__ __forceinline__ void mma_f16_ss(uint32_t d, uint64_t a, uint64_t b,
                                           uint32_t idesc, uint32_t en)
{
    asm volatile(
        "{\n\t"
        ".reg .pred p;\n\t"
        "setp.ne.u32 p, %4, 0;\n\t"
        "tcgen05.mma.cta_group::1.kind::f16 [%0], %1, %2, %3, {%5, %5, %5, %5}, p;\n\t"
        "}"
        :: "r"(d), "l"(a), "l"(b), "r"(idesc), "r"(en), "r"(0u)
        : "memory");
}

__device__ __forceinline__ void mma_f16_ts(uint32_t d, uint32_t a_tmem, uint64_t b,
                                           uint32_t idesc, uint32_t en)
{
    asm volatile(
        "{\n\t"
        ".reg .pred p;\n\t"
        "setp.ne.u32 p, %4, 0;\n\t"
        "tcgen05.mma.cta_group::1.kind::f16 [%0], [%1], %2, %3, {%5, %5, %5, %5}, p;\n\t"
        "}"
        :: "r"(d), "r"(a_tmem), "l"(b), "r"(idesc), "r"(en), "r"(0u)
        : "memory");
}

#endif  // HAS_TCGEN05

// idesc: F32 acc, BF16 x BF16, M=128, N=256
static constexpr uint32_t IDESC =
    (1u << 4) | (1u << 7) | (1u << 10) | ((HID / 8) << 17) | ((128 / 16) << 24);

// ---------------------------------------------------------------------------
// scratch buffers
// ---------------------------------------------------------------------------
__device__ float g_xin[(size_t)MAXN * INCH];
__device__ float g_agg[(size_t)MAXN * INCH];          // overflow-only path
__device__ int   g_cnt[MAXN];
__device__ int   g_eidx[(size_t)MAXN * CAP];
__device__ __nv_bfloat16 g_a1[(size_t)MAXN * 256];
__device__ __nv_bfloat16 g_xs[(size_t)MAXN * 256];
__device__ __nv_bfloat16 g_wt1[(size_t)HID * 384];
__device__ __nv_bfloat16 g_wt2[(size_t)HID * 768];
__device__ __nv_bfloat16 g_wt3[(size_t)HID * 1152];
__device__ __nv_bfloat16 g_wt4[(size_t)HID * 768];

__device__ __forceinline__ void split_bf16(float v, __nv_bfloat16& h, __nv_bfloat16& l)
{
    h = __float2bfloat16(v);
    l = __float2bfloat16(v - __bfloat162float(h));
}

__device__ __forceinline__ float apply_act(float v, int ACT)
{
    if (ACT == 1) {
        v = fmaxf(v, 0.f);
    } else if (ACT == 2) {
        float e = __expf(-2.0f * v);
        v = (v > 0.f) ? __fdividef(1.f - e, 1.f + e) : 0.f;
    } else if (ACT == 3) {
        v = (v > 0.f) ? v : 0.2f * v;
    }
    return v;
}

// ---------------------------------------------------------------------------
// K1: build x_in + xs split; zero agg + cnt
// ---------------------------------------------------------------------------
__global__ void build_xin_kernel(const float* __restrict__ x,
                                 const float* __restrict__ t,
                                 float* __restrict__ xin,
                                 float* __restrict__ agg,
                                 __nv_bfloat16* __restrict__ xs,
                                 int* __restrict__ cnt,
                                 int M)
{
    int idx = blockIdx.x * blockDim.x + threadIdx.x;
    int total = M * INCH;
    if (idx >= total) return;
    if (idx < M) cnt[idx] = 0;
    int row = idx >> 7;
    int col = idx & 127;
    float v = (col < 127) ? x[(size_t)row * 127 + col] : t[row];
    xin[idx] = v;
    agg[idx] = 0.0f;
    __nv_bfloat16 h, l;
    split_bf16(v, h, l);
    xs[(size_t)row * 256 + col] = h;
    xs[(size_t)row * 256 + 128 + col] = l;
}

// ---------------------------------------------------------------------------
// K2: bucket fill — eidx[dst][slot] = src; overflow -> direct scatter
// ---------------------------------------------------------------------------
__device__ __forceinline__ void red_add_v4(float* addr, float4 v)
{
    asm volatile("red.global.add.v4.f32 [%0], {%1,%2,%3,%4};"
                 :: "l"(addr), "f"(v.x), "f"(v.y), "f"(v.z), "f"(v.w)
                 : "memory");
}

__global__ void fill_kernel(const int* __restrict__ src,
                            const int* __restrict__ dst,
                            const float* __restrict__ xin,
                            float* __restrict__ agg,
                            int* __restrict__ cnt,
                            int* __restrict__ eidx,
                            int E)
{
    int e = blockIdx.x * blockDim.x + threadIdx.x;
    if (e >= E) return;
    int d = dst[e];
    int s = src[e];
    int slot = atomicAdd(cnt + d, 1);
    if (slot < CAP) {
        eidx[(size_t)d * CAP + slot] = s;
    } else {
        const float4* ps = reinterpret_cast<const float4*>(xin + (size_t)s * INCH);
        float* pd = agg + (size_t)d * INCH;
        #pragma unroll 4
        for (int i = 0; i < 32; i++)
            red_add_v4(pd + i * 4, ps[i]);
    }
}

// ---------------------------------------------------------------------------
// K3: pull aggregation (warp/node) -> a1 split ; weight prep as extra blocks
// ---------------------------------------------------------------------------
__device__ __forceinline__ void prep_one(const float* __restrict__ W,
                                         __nv_bfloat16* __restrict__ Wt,
                                         int K, int idx)
{
    int Ktot = 3 * K;
    int n  = idx / Ktot;
    int kp = idx - n * Ktot;
    int seg = kp / K;
    int k   = kp - seg * K;
    float w = W[(size_t)k * HID + n];
    __nv_bfloat16 h, l;
    split_bf16(w, h, l);
    Wt[idx] = (seg == 1) ? l : h;
}

__global__ void pull_prep_kernel(const float* __restrict__ xin,
                                 const float* __restrict__ agg,
                                 const int* __restrict__ cnt,
                                 const int* __restrict__ eidx,
                                 __nv_bfloat16* __restrict__ a1,
                                 const float* __restrict__ W1,
                                 const float* __restrict__ W2,
                                 const float* __restrict__ P1,
                                 const float* __restrict__ P2,
                                 __nv_bfloat16* __restrict__ wt1,
                                 __nv_bfloat16* __restrict__ wt2,
                                 __nv_bfloat16* __restrict__ wt3,
                                 __nv_bfloat16* __restrict__ wt4,
                                 int M, int pullBlocks)
{
    if ((int)blockIdx.x >= pullBlocks) {
        int idx = ((int)blockIdx.x - pullBlocks) * 256 + threadIdx.x;
        const int s1 = HID * 384;
        const int s2 = s1 + HID * 768;
        const int s3 = s2 + HID * 1152;
        const int s4 = s3 + HID * 768;
        if (idx < s1)       prep_one(W1, wt1, 128, idx);
        else if (idx < s2)  prep_one(W2, wt2, 256, idx - s1);
        else if (idx < s3)  prep_one(P1, wt3, 384, idx - s2);
        else if (idx < s4)  prep_one(P2, wt4, 256, idx - s3);
        return;
    }
    int node = (blockIdx.x * blockDim.x + threadIdx.x) >> 5;
    int lane = threadIdx.x & 31;
    if (node >= M) return;
    float4 acc = *reinterpret_cast<const float4*>(xin + (size_t)node * INCH + lane * 4);
    {
        float4 o = *reinterpret_cast<const float4*>(agg + (size_t)node * INCH + lane * 4);
        acc.x += o.x; acc.y += o.y; acc.z += o.z; acc.w += o.w;
    }
    float4 acc2 = make_float4(0.f, 0.f, 0.f, 0.f);
    const int n = min(cnt[node], CAP);
    const int* bucket = eidx + (size_t)node * CAP;
    int j = 0;
    for (; j + 1 < n; j += 2) {
        int s0 = __ldg(bucket + j);
        int s1 = __ldg(bucket + j + 1);
        float4 v0 = __ldg(reinterpret_cast<const float4*>(xin + (size_t)s0 * INCH) + lane);
        float4 v1 = __ldg(reinterpret_cast<const float4*>(xin + (size_t)s1 * INCH) + lane);
        acc.x += v0.x; acc.y += v0.y; acc.z += v0.z; acc.w += v0.w;
        acc2.x += v1.x; acc2.y += v1.y; acc2.z += v1.z; acc2.w += v1.w;
    }
    if (j < n) {
        int s0 = __ldg(bucket + j);
        float4 v0 = __ldg(reinterpret_cast<const float4*>(xin + (size_t)s0 * INCH) + lane);
        acc.x += v0.x; acc.y += v0.y; acc.z += v0.z; acc.w += v0.w;
    }
    float f[4] = {acc.x + acc2.x, acc.y + acc2.y, acc.z + acc2.z, acc.w + acc2.w};
    __nv_bfloat16 h[4], l[4];
    #pragma unroll
    for (int i = 0; i < 4; i++) split_bf16(f[i], h[i], l[i]);
    __nv_bfloat162 h01; h01.x = h[0]; h01.y = h[1];
    __nv_bfloat162 h23; h23.x = h[2]; h23.y = h[3];
    __nv_bfloat162 l01; l01.x = l[0]; l01.y = l[1];
    __nv_bfloat162 l23; l23.x = l[2]; l23.y = l[3];
    __nv_bfloat16* rowp = a1 + (size_t)node * 256 + lane * 4;
    *reinterpret_cast<__nv_bfloat162*>(rowp)       = h01;
    *reinterpret_cast<__nv_bfloat162*>(rowp + 2)   = h23;
    *reinterpret_cast<__nv_bfloat162*>(rowp + 128) = l01;
    *reinterpret_cast<__nv_bfloat162*>(rowp + 130) = l23;
}

// ---------------------------------------------------------------------------
// FUSED 4-layer MLP, warp-specialized: warp 8 = TMA producer (free-running),
// thread 0 = MMA consumer, warps 0-7 = epilogue. 288 threads.
// Layer-end sync is named barrier (warps 0-7 only) so the producer never
// stalls on epilogues; B pipeline stays primed across layer boundaries.
// ---------------------------------------------------------------------------
#define NSTAGE 4
#define ABUF_OFF 1024u
#define SB_OFF(s) (66560u + (uint32_t)(s) * 32768u)
#define SMEM_BYTES (66560u + 4u * 32768u)
#define MB_FULL(s)  (8u + 8u * (uint32_t)(s))
#define MB_EMPTY(s) (40u + 8u * (uint32_t)(s))
#define MB_DONE     72u
#define MB_A        80u
#define MB_XS       88u

__global__ void __launch_bounds__(288)
fused_mlp(const __grid_constant__ CUtensorMap mapA1,
          const __grid_constant__ CUtensorMap mapXS,
          const __grid_constant__ CUtensorMap mapB1,
          const __grid_constant__ CUtensorMap mapB2,
          const __grid_constant__ CUtensorMap mapB3,
          const __grid_constant__ CUtensorMap mapB4,
          const __nv_bfloat16* __restrict__ a1,
          const __nv_bfloat16* __restrict__ xs,
          const __nv_bfloat16* __restrict__ wt1,
          const __nv_bfloat16* __restrict__ wt2,
          const __nv_bfloat16* __restrict__ wt3,
          const __nv_bfloat16* __restrict__ wt4,
          const float* __restrict__ b1, const float* __restrict__ b2,
          const float* __restrict__ pb1, const float* __restrict__ pb2,
          const float* __restrict__ P3, const float* __restrict__ pb3,
          float* __restrict__ out, int M)
{
#if HAS_TCGEN05
    extern __shared__ char smem[];
    const uint32_t sm = smem_to_u32(smem);
    const int tid = threadIdx.x;
    const int wid = tid >> 5;
    const int lane = tid & 31;
    const int bid = blockIdx.x;
    const int row0 = bid * 128;

    if (wid == 0) TCGEN05_ALLOC(sm, 512);
    if (tid == 0) {
        #pragma unroll
        for (int s = 0; s < NSTAGE; s++) {
            MBARRIER_INIT(sm + MB_FULL(s), 1);
            MBARRIER_INIT(sm + MB_EMPTY(s), 1);
        }
        MBARRIER_INIT(sm + MB_DONE, 1);
        MBARRIER_INIT(sm + MB_A, 1);
        MBARRIER_INIT(sm + MB_XS, 1);
        FENCE_PROXY_ASYNC_SHARED_CTA();
    }
    __syncthreads();      // all 9 warps: barriers initialized

    // ---------------- producer warp (warp 8) ----------------
    if (wid == 8) {
        if (lane == 0) {
            // A1 tile
            MBARRIER_EXPECT_TX(sm + MB_A, 65536u);
            #pragma unroll
            for (int i = 0; i < 4; i++)
                TMA_LOAD_2D(sm + ABUF_OFF + i * 16384u, &mapA1, i * 64, row0, sm + MB_A);
            // B chunk stream, gated only by empty barriers
            for (int g = 0; g < 48; g++) {
                if (g == 8) {
                    // ABUF reuse: L1 MMAs retired (first MB_DONE completion)
                    MBARRIER_WAIT_PARITY(sm + MB_DONE, 0);
                    MBARRIER_EXPECT_TX(sm + MB_XS, 65536u);
                    #pragma unroll
                    for (int i = 0; i < 4; i++)
                        TMA_LOAD_2D(sm + ABUF_OFF + i * 16384u, &mapXS, i * 64,
                                    row0, sm + MB_XS);
                }
                const int s = g & 3;
                const int u = g >> 2;
                if (u > 0)
                    MBARRIER_WAIT_PARITY(sm + MB_EMPTY(s), (u - 1) & 1);
                const CUtensorMap* mb;
                int base, nch;
                if (g < 6)       { mb = &mapB1; base = 0;  nch = 6;  }
                else if (g < 18) { mb = &mapB2; base = 6;  nch = 12; }
                else if (g < 36) { mb = &mapB3; base = 18; nch = 18; }
                else             { mb = &mapB4; base = 36; nch = 12; }
                int c = (g - base) + bid % nch;
                if (c >= nch) c -= nch;
                MBARRIER_EXPECT_TX(sm + MB_FULL(s), 32768u);
                TMA_LOAD_2D(sm + SB_OFF(s), mb, c * 64, 0, sm + MB_FULL(s));
            }
        }
        return;   // producer warp done
    }

    // ---------------- warps 0-7: consumer + epilogue ----------------
    uint32_t tmem;
    asm volatile("ld.shared.b32 %0, [%1];" : "=r"(tmem) : "r"(sm));
    const uint32_t A_TM = tmem + 256;

    for (int layer = 0; layer < 4; layer++) {
        int nch, K, pref;
        if (layer == 0)      { nch = 6;  K = 128; pref = 0;  }
        else if (layer == 1) { nch = 12; K = 256; pref = 6;  }
        else if (layer == 2) { nch = 18; K = 384; pref = 18; }
        else                 { nch = 12; K = 256; pref = 36; }
        const int phase = bid % nch;

        if (tid == 0) {
            if (layer == 0) MBARRIER_WAIT_PARITY(sm + MB_A, 0);
            if (layer == 2) MBARRIER_WAIT_PARITY(sm + MB_XS, 0);
            TCGEN05_FENCE_AFTER();
            for (int i = 0; i < nch; i++) {
                const int g = pref + i;
                const int s = g & 3;
                MBARRIER_WAIT_PARITY(sm + MB_FULL(s), (g >> 2) & 1);

                int c = i + phase;
                if (c >= nch) c -= nch;
                const int k0 = c * 64;
                const int sc = (k0 < K) ? k0 : (k0 - K);
                const uint64_t bd = MAKE_SMEM_DESC(sm + SB_OFF(s));

                bool smemA = false;
                uint32_t blk = 0, word = 0;
                if (layer == 0) { smemA = true; blk = (uint32_t)(sc >> 6); }
                else if (layer == 2) {
                    if (sc < 256)      word = (uint32_t)(sc >> 1);
                    else if (sc < 384) { smemA = true; blk = (uint32_t)((sc - 256) >> 6); }
                    else if (sc < 640) word = 128u + (uint32_t)((sc - 384) >> 1);
                    else               { smemA = true; blk = (uint32_t)((sc - 640 + 128) >> 6); }
                } else word = (uint32_t)(sc >> 1);

                if (smemA) {
                    const uint64_t ad = MAKE_SMEM_DESC(sm + ABUF_OFF + blk * 16384u);
                    #pragma unroll
                    for (int st = 0; st < 4; st++)
                        mma_f16_ss(tmem, ad + st * 2, bd + st * 2, IDESC,
                                   (i > 0 || st > 0) ? 1u : 0u);
                } else {
                    #pragma unroll
                    for (int st = 0; st < 4; st++)
                        mma_f16_ts(tmem, A_TM + word + st * 8, bd + st * 2, IDESC,
                                   (i > 0 || st > 0) ? 1u : 0u);
                }
                TCGEN05_COMMIT(sm + MB_EMPTY(s));
            }
            TCGEN05_COMMIT(sm + MB_DONE);
        }

        MBARRIER_WAIT_PARITY(sm + MB_DONE, layer & 1);
        TCGEN05_FENCE_AFTER();

        const float* bias = (layer == 0) ? b1 : (layer == 1) ? b2
                           : (layer == 2) ? pb1 : pb2;
        const int ACT = (layer == 0) ? 1 : (layer == 1) ? 2 : 3;
        const uint32_t woff = (uint32_t)(wid & 3) << 21;

        if (layer < 3) {
            const int cg = wid >> 2;
            #pragma unroll 1
            for (int b = 0; b < 2; b++) {
                const int gb = cg * 2 + b;
                uint32_t regs[64];
                TCGEN05_LD_32X32B_X32(regs, tmem + gb * 64);
                TCGEN05_LD_32X32B_X32(regs + 32, tmem + gb * 64 + 32);
                TCGEN05_WAIT_LD();
                uint32_t hw[32], lw[32];
                #pragma unroll
                for (int j = 0; j < 64; j += 2) {
                    int col = gb * 64 + j;
                    float v0 = apply_act(__uint_as_float(regs[j])     + __ldg(bias + col), ACT);
                    float v1 = apply_act(__uint_as_float(regs[j + 1]) + __ldg(bias + col + 1), ACT);
                    __nv_bfloat16 h0, l0, h1, l1;
                    split_bf16(v0, h0, l0);
                    split_bf16(v1, h1, l1);
                    __nv_bfloat162 hv; hv.x = h0; hv.y = h1;
                    __nv_bfloat162 lv; lv.x = l0; lv.y = l1;
                    hw[j >> 1] = *reinterpret_cast<uint32_t*>(&hv);
                    lw[j >> 1] = *reinterpret_cast<uint32_t*>(&lv);
                }
                TCGEN05_ST_32X32B_X32(A_TM + gb * 32 + woff, hw);
                TCGEN05_ST_32X32B_X32(A_TM + 128 + gb * 32 + woff, lw);
            }
            TCGEN05_WAIT_ST();
        } else if (wid < 4) {
            const int row = row0 + wid * 32 + lane;
            const bool valid = (row < M);
            float gsum = 0.0f;
            #pragma unroll 1
            for (int b = 0; b < 4; b++) {
                uint32_t regs[64];
                TCGEN05_LD_32X32B_X32(regs, tmem + b * 64);
                TCGEN05_LD_32X32B_X32(regs + 32, tmem + b * 64 + 32);
                TCGEN05_WAIT_LD();
                #pragma unroll
                for (int j = 0; j < 64; j += 2) {
                    int col = b * 64 + j;
                    float v0 = apply_act(__uint_as_float(regs[j])     + __ldg(bias + col), ACT);
                    float v1 = apply_act(__uint_as_float(regs[j + 1]) + __ldg(bias + col + 1), ACT);
                    gsum += v0 * __ldg(P3 + col) + v1 * __ldg(P3 + col + 1);
                }
            }
            if (valid) {
                out[row] = 0.0f;
                out[(size_t)M + row] = gsum + __ldg(pb3);
            }
        }
        TCGEN05_FENCE_BEFORE();
        // named barrier: warps 0-7 only (producer must not participate)
        asm volatile("bar.sync 1, 256;" ::: "memory");
    }

    if (wid == 0) {
        TCGEN05_RELINQUISH_ALLOC_PERMIT();
        TCGEN05_DEALLOC(tmem, 512);
    }
#else
    // ---- fallback (non arch-specific pass only): correct, slow SIMT path
    const int tid = threadIdx.x;
    if (tid >= 128) return;
    const int row = blockIdx.x * 128 + tid;
    if (row >= M) return;
    float cur[384], nxt[256];
    for (int k = 0; k < 128; k++)
        cur[k] = __bfloat162float(a1[(size_t)row * 256 + k])
               + __bfloat162float(a1[(size_t)row * 256 + 128 + k]);
    for (int n = 0; n < 256; n++) {
        float s = 0.f;
        for (int k = 0; k < 128; k++)
            s += cur[k] * (__bfloat162float(wt1[(size_t)n * 384 + k])
                         + __bfloat162float(wt1[(size_t)n * 384 + 128 + k]));
        nxt[n] = apply_act(s + b1[n], 1);
    }
    for (int n = 0; n < 256; n++) cur[n] = nxt[n];
    for (int n = 0; n < 256; n++) {
        float s = 0.f;
        for (int k = 0; k < 256; k++)
            s += cur[k] * (__bfloat162float(wt2[(size_t)n * 768 + k])
                         + __bfloat162float(wt2[(size_t)n * 768 + 256 + k]));
        nxt[n] = apply_act(s + b2[n], 2);
    }
    for (int n = 0; n < 256; n++) cur[n] = nxt[n];
    for (int k = 0; k < 128; k++)
        cur[256 + k] = __bfloat162float(xs[(size_t)row * 256 + k])
                     + __bfloat162float(xs[(size_t)row * 256 + 128 + k]);
    for (int n = 0; n < 256; n++) {
        float s = 0.f;
        for (int k = 0; k < 384; k++)
            s += cur[k] * (__bfloat162float(wt3[(size_t)n * 1152 + k])
                         + __bfloat162float(wt3[(size_t)n * 1152 + 384 + k]));
        nxt[n] = apply_act(s + pb1[n], 3);
    }
    for (int n = 0; n < 256; n++) cur[n] = nxt[n];
    float gsum = 0.f;
    for (int n = 0; n < 256; n++) {
        float s = 0.f;
        for (int k = 0; k < 256; k++)
            s += cur[k] * (__bfloat162float(wt4[(size_t)n * 768 + k])
                         + __bfloat162float(wt4[(size_t)n * 768 + 256 + k]));
        gsum += apply_act(s + pb2[n], 3) * P3[n];
    }
    out[row] = 0.0f;
    out[(size_t)M + row] = gsum + pb3[0];
#endif
}

// ---------------------------------------------------------------------------
// host: tensormap encoding via runtime-queried driver entry point (no -lcuda)
// ---------------------------------------------------------------------------
typedef CUresult (*EncodeTiledFn)(
    CUtensorMap*, CUtensorMapDataType, cuuint32_t, void*,
    const cuuint64_t*, const cuuint64_t*, const cuuint32_t*, const cuuint32_t*,
    CUtensorMapInterleave, CUtensorMapSwizzle, CUtensorMapL2promotion,
    CUtensorMapFloatOOBfill);

static EncodeTiledFn get_encoder()
{
    void* fn = nullptr;
    cudaDriverEntryPointQueryResult qr;
    cudaGetDriverEntryPointByVersion("cuTensorMapEncodeTiled", &fn, 12000,
                                     cudaEnableDefault, &qr);
    return (EncodeTiledFn)fn;
}

static void make_map(EncodeTiledFn enc, CUtensorMap* m, void* base,
                     uint64_t inner, uint64_t outer, uint32_t box0, uint32_t box1)
{
    cuuint64_t dims[2]    = {(cuuint64_t)inner, (cuuint64_t)outer};
    cuuint64_t strides[1] = {(cuuint64_t)(inner * 2)};
    cuuint32_t box[2]     = {(cuuint32_t)box0, (cuuint32_t)box1};
    cuuint32_t es[2]      = {1, 1};
    enc(m, CU_TENSOR_MAP_DATA_TYPE_BFLOAT16, 2, base, dims, strides, box, es,
        CU_TENSOR_MAP_INTERLEAVE_NONE, CU_TENSOR_MAP_SWIZZLE_128B,
        CU_TENSOR_MAP_L2_PROMOTION_L2_128B, CU_TENSOR_MAP_FLOAT_OOB_FILL_NONE);
}

// ---------------------------------------------------------------------------
extern "C" void kernel_launch(void* const* d_in, const int* in_sizes, int n_in,
                              void* d_out, int out_size)
{
    const float* x   = (const float*)d_in[0];
    const float* t   = (const float*)d_in[1];
    const int*   ei  = (const int*)d_in[3];
    const float* W1  = (const float*)d_in[4];
    const float* b1  = (const float*)d_in[5];
    const float* W2  = (const float*)d_in[6];
    const float* b2  = (const float*)d_in[7];
    const float* P1  = (const float*)d_in[8];
    const float* pb1 = (const float*)d_in[9];
    const float* P2  = (const float*)d_in[10];
    const float* pb2 = (const float*)d_in[11];
    const float* P3  = (const float*)d_in[12];
    const float* pb3 = (const float*)d_in[13];
    float* out = (float*)d_out;

    const int M = in_sizes[1];
    const int E = in_sizes[3] / 2;

    float *xin, *agg;
    int *cnt, *eidx;
    __nv_bfloat16 *a1, *xs, *wt1, *wt2, *wt3, *wt4;
    cudaGetSymbolAddress((void**)&xin, g_xin);
    cudaGetSymbolAddress((void**)&agg, g_agg);
    cudaGetSymbolAddress((void**)&cnt, g_cnt);
    cudaGetSymbolAddress((void**)&eidx, g_eidx);
    cudaGetSymbolAddress((void**)&a1,  g_a1);
    cudaGetSymbolAddress((void**)&xs,  g_xs);
    cudaGetSymbolAddress((void**)&wt1, g_wt1);
    cudaGetSymbolAddress((void**)&wt2, g_wt2);
    cudaGetSymbolAddress((void**)&wt3, g_wt3);
    cudaGetSymbolAddress((void**)&wt4, g_wt4);

    EncodeTiledFn enc = get_encoder();
    CUtensorMap mA1, mXS, mB1, mB2, mB3, mB4;
    make_map(enc, &mA1, a1, 256, (uint64_t)M, 64, 128);
    make_map(enc, &mXS, xs, 256, (uint64_t)M, 64, 128);
    make_map(enc, &mB1, wt1, 384,  256, 64, 256);
    make_map(enc, &mB2, wt2, 768,  256, 64, 256);
    make_map(enc, &mB3, wt3, 1152, 256, 64, 256);
    make_map(enc, &mB4, wt4, 768,  256, 64, 256);

    cudaFuncSetAttribute(fused_mlp,
                         cudaFuncAttributeMaxDynamicSharedMemorySize, SMEM_BYTES);

    // 1: build x_in, xs split; zero agg + cnt
    {
        int total = M * INCH;
        build_xin_kernel<<<(total + 255) / 256, 256>>>(x, t, xin, agg, xs, cnt, M);
    }
    // 2: bucket fill
    fill_kernel<<<(E + 255) / 256, 256>>>(ei, ei + E, xin, agg, cnt, eidx, E);
    // 3: pull aggregation -> a1 split ; weight prep appended
    {
        int pullBlocks = (M * 32 + 255) / 256;
        int prepBlocks = (HID * (384 + 768 + 1152 + 768) + 255) / 256;
        pull_prep_kernel<<<pullBlocks + prepBlocks, 256>>>(
            xin, agg, cnt, eidx, a1,
            W1, W2, P1, P2, wt1, wt2, wt3, wt4, M, pullBlocks);
    }
    // 4: fused 4-layer MLP + gemv (warp-specialized producer)
    {
        int tiles = (M + 127) / 128;
        fused_mlp<<<tiles, 288, SMEM_BYTES>>>(
            mA1, mXS, mB1, mB2, mB3, mB4,
            a1, xs, wt1, wt2, wt3, wt4,
            b1, b2, pb1, pb2, P3, pb3, out, M);
    }
}

// round 16
// speedup vs baseline: 1.3826x; 1.3826x over previous
#include <cuda_runtime.h>
#include <cuda.h>
#include <cuda_bf16.h>
#include <math.h>
#include <cstdint>

#define MAXN 50000
#define INCH 128
#define HID  256
#define CAP  64

#if defined(__CUDA_ARCH__) && (defined(__CUDA_ARCH_FEAT_SM103_ALL) || defined(__CUDA_ARCH_FEAT_SM100_ALL))
#define HAS_TCGEN05 1
#else
#define HAS_TCGEN05 0
#endif

// ---------------------------------------------------------------------------
// PTX helpers (guarded: only expanded in the sm_103a pass)
// ---------------------------------------------------------------------------
#if HAS_TCGEN05

__device__ __forceinline__ uint32_t smem_to_u32(const void* smem_ptr) {
    uint32_t addr;
    asm("{ .reg .u64 tmp; cvta.to.shared.u64 tmp, %1; cvt.u32.u64 %0, tmp; }"
        : "=r"(addr) : "l"(smem_ptr));
    return addr;
}

#define TCGEN05_ALLOC(smem_result_addr, nCols) \
    asm volatile( \
        "tcgen05.alloc.cta_group::1.sync.aligned.shared::cta.b32 [%0], %1;" \
        :: "r"((uint32_t)(smem_result_addr)), "r"((uint32_t)(nCols)) \
        : "memory")

#define TCGEN05_DEALLOC(tmem_addr, nCols) \
    asm volatile( \
        "tcgen05.dealloc.cta_group::1.sync.aligned.b32 %0, %1;" \
        :: "r"(tmem_addr), "r"((uint32_t)(nCols)))

#define TCGEN05_RELINQUISH_ALLOC_PERMIT() \
    asm volatile("tcgen05.relinquish_alloc_permit.cta_group::1.sync.aligned;")

#define TCGEN05_COMMIT(mbar_smem_addr) \
    asm volatile( \
        "tcgen05.commit.cta_group::1.mbarrier::arrive::one.shared::cluster.b64 [%0];" \
        :: "r"((uint32_t)(mbar_smem_addr)) \
        : "memory")

#define TCGEN05_WAIT_LD() \
    asm volatile("tcgen05.wait::ld.sync.aligned;" ::: "memory")

#define TCGEN05_WAIT_ST() \
    asm volatile("tcgen05.wait::st.sync.aligned;" ::: "memory")

#define TCGEN05_FENCE_BEFORE() \
    asm volatile("tcgen05.fence::before_thread_sync;" ::: "memory")

#define TCGEN05_FENCE_AFTER() \
    asm volatile("tcgen05.fence::after_thread_sync;" ::: "memory")

#define FENCE_PROXY_ASYNC_SHARED_CTA() \
    asm volatile("fence.proxy.async.shared::cta;" ::: "memory")

#define MBARRIER_INIT(mbar_smem_addr, count) \
    asm volatile( \
        "mbarrier.init.shared.b64 [%0], %1;" \
        :: "r"((uint32_t)(mbar_smem_addr)), "r"((uint32_t)(count)) \
        : "memory")

#define MBARRIER_EXPECT_TX(mbar_smem_addr, tx_bytes) \
    asm volatile( \
        "mbarrier.arrive.expect_tx.shared.b64 _, [%0], %1;" \
        :: "r"((uint32_t)(mbar_smem_addr)), "r"((uint32_t)(tx_bytes)) \
        : "memory")

#define MBARRIER_WAIT_PARITY(mbar_smem_addr, phase_parity) do { \
    uint32_t _mbar = (uint32_t)(mbar_smem_addr); \
    uint32_t _parity = (uint32_t)(phase_parity); \
    uint32_t _done; \
    asm volatile( \
        "{\n\t" \
        ".reg .pred p;\n\t" \
        "mbarrier.try_wait.parity.acquire.cta.shared::cta.b64 p, [%1], %2;\n\t" \
        "selp.b32 %0, 1, 0, p;\n\t" \
        "}" \
        : "=r"(_done) : "r"(_mbar), "r"(_parity) : "memory"); \
    if (!_done) { \
        asm volatile( \
            "{\n\t" \
            ".reg .pred P1;\n\t" \
            "WAIT_LOOP_%=:\n\t" \
            "mbarrier.try_wait.parity.acquire.cta.shared::cta.b64 P1, [%0], %1, 0x989680;\n\t" \
            "@P1 bra.uni WAIT_DONE_%=;\n\t" \
            "bra.uni WAIT_LOOP_%=;\n\t" \
            "WAIT_DONE_%=:\n\t" \
            "}" \
            :: "r"(_mbar), "r"(_parity) : "memory"); \
    } \
} while(0)

#define TMA_LOAD_2D(smem_addr, map_ptr, cx, cy, mbar) \
    asm volatile( \
        "cp.async.bulk.tensor.2d.shared::cta.global.tile.mbarrier::complete_tx::bytes " \
        "[%0], [%1, {%2, %3}], [%4];" \
        :: "r"((uint32_t)(smem_addr)), "l"(map_ptr), "r"((int)(cx)), "r"((int)(cy)), \
           "r"((uint32_t)(mbar)) \
        : "memory")

#define TCGEN05_LD_32X32B_X32(r, tmem_addr) \
    asm volatile( \
        "tcgen05.ld.sync.aligned.32x32b.x32.b32 " \
        "{%0, %1, %2, %3, %4, %5, %6, %7, " \
        " %8, %9, %10, %11, %12, %13, %14, %15, " \
        " %16, %17, %18, %19, %20, %21, %22, %23, " \
        " %24, %25, %26, %27, %28, %29, %30, %31}, [%32];" \
        : "=r"((r)[0]),  "=r"((r)[1]),  "=r"((r)[2]),  "=r"((r)[3]), \
          "=r"((r)[4]),  "=r"((r)[5]),  "=r"((r)[6]),  "=r"((r)[7]), \
          "=r"((r)[8]),  "=r"((r)[9]),  "=r"((r)[10]), "=r"((r)[11]), \
          "=r"((r)[12]), "=r"((r)[13]), "=r"((r)[14]), "=r"((r)[15]), \
          "=r"((r)[16]), "=r"((r)[17]), "=r"((r)[18]), "=r"((r)[19]), \
          "=r"((r)[20]), "=r"((r)[21]), "=r"((r)[22]), "=r"((r)[23]), \
          "=r"((r)[24]), "=r"((r)[25]), "=r"((r)[26]), "=r"((r)[27]), \
          "=r"((r)[28]), "=r"((r)[29]), "=r"((r)[30]), "=r"((r)[31]) \
        : "r"(tmem_addr))

#define TCGEN05_ST_32X32B_X32(tmem_addr, r) \
    asm volatile( \
        "tcgen05.st.sync.aligned.32x32b.x32.b32 [%0], " \
        "{%1, %2, %3, %4, %5, %6, %7, %8, " \
        " %9, %10, %11, %12, %13, %14, %15, %16, " \
        " %17, %18, %19, %20, %21, %22, %23, %24, " \
        " %25, %26, %27, %28, %29, %30, %31, %32};" \
        :: "r"(tmem_addr), \
           "r"((r)[0]),  "r"((r)[1]),  "r"((r)[2]),  "r"((r)[3]), \
           "r"((r)[4]),  "r"((r)[5]),  "r"((r)[6]),  "r"((r)[7]), \
           "r"((r)[8]),  "r"((r)[9]),  "r"((r)[10]), "r"((r)[11]), \
           "r"((r)[12]), "r"((r)[13]), "r"((r)[14]), "r"((r)[15]), \
           "r"((r)[16]), "r"((r)[17]), "r"((r)[18]), "r"((r)[19]), \
           "r"((r)[20]), "r"((r)[21]), "r"((r)[22]), "r"((r)[23]), \
           "r"((r)[24]), "r"((r)[25]), "r"((r)[26]), "r"((r)[27]), \
           "r"((r)[28]), "r"((r)[29]), "r"((r)[30]), "r"((r)[31]) \
        : "memory")

static constexpr uint64_t SMEM_DESC_BASE_SW128 =
    (uint64_t(2)  << 61)
    | (uint64_t(1) << 46)
    | (uint64_t(64) << 32)
    | (uint64_t(1) << 16);

#define MAKE_SMEM_DESC(base_addr) \
    (SMEM_DESC_BASE_SW128 | ((uint64_t)((base_addr) >> 4) & 0x3FFF))

__device__ __forceinline__ void mma_f16_ss(uint32_t d, uint64_t a, uint64_t b,
                                           uint32_t idesc, uint32_t en)
{
    asm volatile(
        "{\n\t"
        ".reg .pred p;\n\t"
        "setp.ne.u32 p, %4, 0;\n\t"
        "tcgen05.mma.cta_group::1.kind::f16 [%0], %1, %2, %3, {%5, %5, %5, %5}, p;\n\t"
        "}"
        :: "r"(d), "l"(a), "l"(b), "r"(idesc), "r"(en), "r"(0u)
        : "memory");
}

__device__ __forceinline__ void mma_f16_ts(uint32_t d, uint32_t a_tmem, uint64_t b,
                                           uint32_t idesc, uint32_t en)
{
    asm volatile(
        "{\n\t"
        ".reg .pred p;\n\t"
        "setp.ne.u32 p, %4, 0;\n\t"
        "tcgen05.mma.cta_group::1.kind::f16 [%0], [%1], %2, %3, {%5, %5, %5, %5}, p;\n\t"
        "}"
        :: "r"(d), "r"(a_tmem), "l"(b), "r"(idesc), "r"(en), "r"(0u)
        : "memory");
}

// fast split: hi pair by byte-perm (truncation), lo pair by one packed cvt
__device__ __forceinline__ void split_pair_fast(float v0, float v1,
                                                uint32_t& hi_pair, uint32_t& lo_pair)
{
    uint32_t u0 = __float_as_uint(v0);
    uint32_t u1 = __float_as_uint(v1);
    asm("prmt.b32 %0, %1, %2, 0x7632;" : "=r"(hi_pair) : "r"(u0), "r"(u1));
    float lo0 = v0 - __uint_as_float(u0 & 0xFFFF0000u);
    float lo1 = v1 - __uint_as_float(u1 & 0xFFFF0000u);
    asm("cvt.rn.satfinite.bf16x2.f32 %0, %1, %2;"
        : "=r"(lo_pair) : "f"(lo1), "f"(lo0));
}

#endif  // HAS_TCGEN05

// idesc: F32 acc, BF16 x BF16, M=128, N=256
static constexpr uint32_t IDESC =
    (1u << 4) | (1u << 7) | (1u << 10) | ((HID / 8) << 17) | ((128 / 16) << 24);

// ---------------------------------------------------------------------------
// scratch buffers
// ---------------------------------------------------------------------------
__device__ float g_xin[(size_t)MAXN * INCH];
__device__ float g_agg[(size_t)MAXN * INCH];          // overflow-only path
__device__ int   g_cnt[MAXN];
__device__ int   g_eidx[(size_t)MAXN * CAP];
__device__ __nv_bfloat16 g_a1[(size_t)MAXN * 256];
__device__ __nv_bfloat16 g_xs[(size_t)MAXN * 256];
__device__ __nv_bfloat16 g_wt1[(size_t)HID * 384];
__device__ __nv_bfloat16 g_wt2[(size_t)HID * 768];
__device__ __nv_bfloat16 g_wt3[(size_t)HID * 1152];
__device__ __nv_bfloat16 g_wt4[(size_t)HID * 768];

__device__ __forceinline__ void split_bf16(float v, __nv_bfloat16& h, __nv_bfloat16& l)
{
    h = __float2bfloat16(v);
    l = __float2bfloat16(v - __bfloat162float(h));
}

__device__ __forceinline__ float apply_act(float v, int ACT)
{
    if (ACT == 1) {
        v = fmaxf(v, 0.f);
    } else if (ACT == 2) {
        float e = __expf(-2.0f * v);
        v = (v > 0.f) ? __fdividef(1.f - e, 1.f + e) : 0.f;
    } else if (ACT == 3) {
        v = (v > 0.f) ? v : 0.2f * v;
    }
    return v;
}

// ---------------------------------------------------------------------------
// K1: build x_in + xs split; zero agg + cnt
// ---------------------------------------------------------------------------
__global__ void build_xin_kernel(const float* __restrict__ x,
                                 const float* __restrict__ t,
                                 float* __restrict__ xin,
                                 float* __restrict__ agg,
                                 __nv_bfloat16* __restrict__ xs,
                                 int* __restrict__ cnt,
                                 int M)
{
    int idx = blockIdx.x * blockDim.x + threadIdx.x;
    int total = M * INCH;
    if (idx >= total) return;
    if (idx < M) cnt[idx] = 0;
    int row = idx >> 7;
    int col = idx & 127;
    float v = (col < 127) ? x[(size_t)row * 127 + col] : t[row];
    xin[idx] = v;
    agg[idx] = 0.0f;
    __nv_bfloat16 h, l;
    split_bf16(v, h, l);
    xs[(size_t)row * 256 + col] = h;
    xs[(size_t)row * 256 + 128 + col] = l;
}

// ---------------------------------------------------------------------------
// K2: bucket fill — eidx[dst][slot] = src; overflow -> direct scatter
// ---------------------------------------------------------------------------
__device__ __forceinline__ void red_add_v4(float* addr, float4 v)
{
    asm volatile("red.global.add.v4.f32 [%0], {%1,%2,%3,%4};"
                 :: "l"(addr), "f"(v.x), "f"(v.y), "f"(v.z), "f"(v.w)
                 : "memory");
}

__global__ void fill_kernel(const int* __restrict__ src,
                            const int* __restrict__ dst,
                            const float* __restrict__ xin,
                            float* __restrict__ agg,
                            int* __restrict__ cnt,
                            int* __restrict__ eidx,
                            int E)
{
    int e = blockIdx.x * blockDim.x + threadIdx.x;
    if (e >= E) return;
    int d = dst[e];
    int s = src[e];
    int slot = atomicAdd(cnt + d, 1);
    if (slot < CAP) {
        eidx[(size_t)d * CAP + slot] = s;
    } else {
        const float4* ps = reinterpret_cast<const float4*>(xin + (size_t)s * INCH);
        float* pd = agg + (size_t)d * INCH;
        #pragma unroll 4
        for (int i = 0; i < 32; i++)
            red_add_v4(pd + i * 4, ps[i]);
    }
}

// ---------------------------------------------------------------------------
// K3: pull aggregation (warp/node) -> a1 split ; weight prep as extra blocks
// ---------------------------------------------------------------------------
__device__ __forceinline__ void prep_one(const float* __restrict__ W,
                                         __nv_bfloat16* __restrict__ Wt,
                                         int K, int idx)
{
    int Ktot = 3 * K;
    int n  = idx / Ktot;
    int kp = idx - n * Ktot;
    int seg = kp / K;
    int k   = kp - seg * K;
    float w = W[(size_t)k * HID + n];
    __nv_bfloat16 h, l;
    split_bf16(w, h, l);
    Wt[idx] = (seg == 1) ? l : h;
}

__global__ void pull_prep_kernel(const float* __restrict__ xin,
                                 const float* __restrict__ agg,
                                 const int* __restrict__ cnt,
                                 const int* __restrict__ eidx,
                                 __nv_bfloat16* __restrict__ a1,
                                 const float* __restrict__ W1,
                                 const float* __restrict__ W2,
                                 const float* __restrict__ P1,
                                 const float* __restrict__ P2,
                                 __nv_bfloat16* __restrict__ wt1,
                                 __nv_bfloat16* __restrict__ wt2,
                                 __nv_bfloat16* __restrict__ wt3,
                                 __nv_bfloat16* __restrict__ wt4,
                                 int M, int pullBlocks)
{
    if ((int)blockIdx.x >= pullBlocks) {
        int idx = ((int)blockIdx.x - pullBlocks) * 256 + threadIdx.x;
        const int s1 = HID * 384;
        const int s2 = s1 + HID * 768;
        const int s3 = s2 + HID * 1152;
        const int s4 = s3 + HID * 768;
        if (idx < s1)       prep_one(W1, wt1, 128, idx);
        else if (idx < s2)  prep_one(W2, wt2, 256, idx - s1);
        else if (idx < s3)  prep_one(P1, wt3, 384, idx - s2);
        else if (idx < s4)  prep_one(P2, wt4, 256, idx - s3);
        return;
    }
    int node = (blockIdx.x * blockDim.x + threadIdx.x) >> 5;
    int lane = threadIdx.x & 31;
    if (node >= M) return;
    float4 acc = *reinterpret_cast<const float4*>(xin + (size_t)node * INCH + lane * 4);
    {
        float4 o = *reinterpret_cast<const float4*>(agg + (size_t)node * INCH + lane * 4);
        acc.x += o.x; acc.y += o.y; acc.z += o.z; acc.w += o.w;
    }
    float4 acc2 = make_float4(0.f, 0.f, 0.f, 0.f);
    const int n = min(cnt[node], CAP);
    const int* bucket = eidx + (size_t)node * CAP;
    int j = 0;
    for (; j + 1 < n; j += 2) {
        int s0 = __ldg(bucket + j);
        int s1 = __ldg(bucket + j + 1);
        float4 v0 = __ldg(reinterpret_cast<const float4*>(xin + (size_t)s0 * INCH) + lane);
        float4 v1 = __ldg(reinterpret_cast<const float4*>(xin + (size_t)s1 * INCH) + lane);
        acc.x += v0.x; acc.y += v0.y; acc.z += v0.z; acc.w += v0.w;
        acc2.x += v1.x; acc2.y += v1.y; acc2.z += v1.z; acc2.w += v1.w;
    }
    if (j < n) {
        int s0 = __ldg(bucket + j);
        float4 v0 = __ldg(reinterpret_cast<const float4*>(xin + (size_t)s0 * INCH) + lane);
        acc.x += v0.x; acc.y += v0.y; acc.z += v0.z; acc.w += v0.w;
    }
    float f[4] = {acc.x + acc2.x, acc.y + acc2.y, acc.z + acc2.z, acc.w + acc2.w};
    __nv_bfloat16 h[4], l[4];
    #pragma unroll
    for (int i = 0; i < 4; i++) split_bf16(f[i], h[i], l[i]);
    __nv_bfloat162 h01; h01.x = h[0]; h01.y = h[1];
    __nv_bfloat162 h23; h23.x = h[2]; h23.y = h[3];
    __nv_bfloat162 l01; l01.x = l[0]; l01.y = l[1];
    __nv_bfloat162 l23; l23.x = l[2]; l23.y = l[3];
    __nv_bfloat16* rowp = a1 + (size_t)node * 256 + lane * 4;
    *reinterpret_cast<__nv_bfloat162*>(rowp)       = h01;
    *reinterpret_cast<__nv_bfloat162*>(rowp + 2)   = h23;
    *reinterpret_cast<__nv_bfloat162*>(rowp + 128) = l01;
    *reinterpret_cast<__nv_bfloat162*>(rowp + 130) = l23;
}

// ---------------------------------------------------------------------------
// FUSED 4-layer MLP (r13 driver structure) with FAST epilogue:
//   - hi split via prmt (truncation), lo via packed cvt (one instr per pair)
//   - float2 bias / P3 loads
//   - L4 gemv uses all 8 warps (column split, smem combine)
// ---------------------------------------------------------------------------
#define NSTAGE 4
#define ABUF_OFF 1024u
#define SB_OFF(s) (66560u + (uint32_t)(s) * 32768u)
#define SMEM_BYTES (66560u + 4u * 32768u)
#define MB_FULL(s)  (8u + 8u * (uint32_t)(s))
#define MB_EMPTY(s) (40u + 8u * (uint32_t)(s))
#define MB_DONE     72u
#define MB_A        80u
#define MB_XS       88u

__global__ void __launch_bounds__(256)
fused_mlp(const __grid_constant__ CUtensorMap mapA1,
          const __grid_constant__ CUtensorMap mapXS,
          const __grid_constant__ CUtensorMap mapB1,
          const __grid_constant__ CUtensorMap mapB2,
          const __grid_constant__ CUtensorMap mapB3,
          const __grid_constant__ CUtensorMap mapB4,
          const __nv_bfloat16* __restrict__ a1,
          const __nv_bfloat16* __restrict__ xs,
          const __nv_bfloat16* __restrict__ wt1,
          const __nv_bfloat16* __restrict__ wt2,
          const __nv_bfloat16* __restrict__ wt3,
          const __nv_bfloat16* __restrict__ wt4,
          const float* __restrict__ b1, const float* __restrict__ b2,
          const float* __restrict__ pb1, const float* __restrict__ pb2,
          const float* __restrict__ P3, const float* __restrict__ pb3,
          float* __restrict__ out, int M)
{
#if HAS_TCGEN05
    extern __shared__ char smem[];
    const uint32_t sm = smem_to_u32(smem);
    const int tid = threadIdx.x;
    const int wid = tid >> 5;
    const int lane = tid & 31;
    const int bid = blockIdx.x;
    const int row0 = bid * 128;

    if (wid == 0) TCGEN05_ALLOC(sm, 512);
    if (tid == 0) {
        #pragma unroll
        for (int s = 0; s < NSTAGE; s++) {
            MBARRIER_INIT(sm + MB_FULL(s), 1);
            MBARRIER_INIT(sm + MB_EMPTY(s), 1);
        }
        MBARRIER_INIT(sm + MB_DONE, 1);
        MBARRIER_INIT(sm + MB_A, 1);
        MBARRIER_INIT(sm + MB_XS, 1);
        FENCE_PROXY_ASYNC_SHARED_CTA();
    }
    __syncthreads();
    uint32_t tmem;
    asm volatile("ld.shared.b32 %0, [%1];" : "=r"(tmem) : "r"(sm));
    const uint32_t A_TM = tmem + 256;

    auto load_chunk = [&](int g) {
        const int s = g & 3;
        const CUtensorMap* mb;
        int base, nch;
        if (g < 6)       { mb = &mapB1; base = 0;  nch = 6;  }
        else if (g < 18) { mb = &mapB2; base = 6;  nch = 12; }
        else if (g < 36) { mb = &mapB3; base = 18; nch = 18; }
        else             { mb = &mapB4; base = 36; nch = 12; }
        int c = (g - base) + bid % nch;
        if (c >= nch) c -= nch;
        MBARRIER_EXPECT_TX(sm + MB_FULL(s), 32768u);
        TMA_LOAD_2D(sm + SB_OFF(s), mb, c * 64, 0, sm + MB_FULL(s));
    };

    if (tid == 0) {
        MBARRIER_EXPECT_TX(sm + MB_A, 65536u);
        #pragma unroll
        for (int i = 0; i < 4; i++)
            TMA_LOAD_2D(sm + ABUF_OFF + i * 16384u, &mapA1, i * 64, row0, sm + MB_A);
        for (int g = 0; g < 4; g++) load_chunk(g);
    }

    for (int layer = 0; layer < 4; layer++) {
        int nch, K, pref;
        if (layer == 0)      { nch = 6;  K = 128; pref = 0;  }
        else if (layer == 1) { nch = 12; K = 256; pref = 6;  }
        else if (layer == 2) { nch = 18; K = 384; pref = 18; }
        else                 { nch = 12; K = 256; pref = 36; }
        const int phase = bid % nch;

        if (tid == 0) {
            if (layer == 0) MBARRIER_WAIT_PARITY(sm + MB_A, 0);
            if (layer == 2) MBARRIER_WAIT_PARITY(sm + MB_XS, 0);
            for (int i = 0; i < nch; i++) {
                const int g = pref + i;
                const int s = g & 3;
                MBARRIER_WAIT_PARITY(sm + MB_FULL(s), (g >> 2) & 1);

                int c = i + phase;
                if (c >= nch) c -= nch;
                const int k0 = c * 64;
                const int sc = (k0 < K) ? k0 : (k0 - K);
                const uint64_t bd = MAKE_SMEM_DESC(sm + SB_OFF(s));

                bool smemA = false;
                uint32_t blk = 0, word = 0;
                if (layer == 0) { smemA = true; blk = (uint32_t)(sc >> 6); }
                else if (layer == 2) {
                    if (sc < 256)      word = (uint32_t)(sc >> 1);
                    else if (sc < 384) { smemA = true; blk = (uint32_t)((sc - 256) >> 6); }
                    else if (sc < 640) word = 128u + (uint32_t)((sc - 384) >> 1);
                    else               { smemA = true; blk = (uint32_t)((sc - 640 + 128) >> 6); }
                } else word = (uint32_t)(sc >> 1);

                if (smemA) {
                    const uint64_t ad = MAKE_SMEM_DESC(sm + ABUF_OFF + blk * 16384u);
                    #pragma unroll
                    for (int st = 0; st < 4; st++)
                        mma_f16_ss(tmem, ad + st * 2, bd + st * 2, IDESC,
                                   (i > 0 || st > 0) ? 1u : 0u);
                } else {
                    #pragma unroll
                    for (int st = 0; st < 4; st++)
                        mma_f16_ts(tmem, A_TM + word + st * 8, bd + st * 2, IDESC,
                                   (i > 0 || st > 0) ? 1u : 0u);
                }
                TCGEN05_COMMIT(sm + MB_EMPTY(s));

                const int r = g - 2;
                if (r >= 0 && g + 2 < 48) {
                    MBARRIER_WAIT_PARITY(sm + MB_EMPTY(r & 3), (r >> 2) & 1);
                    load_chunk(g + 2);
                }
            }
            TCGEN05_COMMIT(sm + MB_DONE);
        }

        MBARRIER_WAIT_PARITY(sm + MB_DONE, layer & 1);
        TCGEN05_FENCE_AFTER();

        if (tid == 0 && layer == 0) {
            MBARRIER_EXPECT_TX(sm + MB_XS, 65536u);
            #pragma unroll
            for (int i = 0; i < 4; i++)
                TMA_LOAD_2D(sm + ABUF_OFF + i * 16384u, &mapXS, i * 64, row0, sm + MB_XS);
        }

        const float* bias = (layer == 0) ? b1 : (layer == 1) ? b2
                           : (layer == 2) ? pb1 : pb2;
        const int ACT = (layer == 0) ? 1 : (layer == 1) ? 2 : 3;
        const uint32_t woff = (uint32_t)(wid & 3) << 21;
        const int cg = wid >> 2;

        if (layer < 3) {
            #pragma unroll 1
            for (int b = 0; b < 2; b++) {
                const int gb = cg * 2 + b;
                uint32_t regs[64];
                TCGEN05_LD_32X32B_X32(regs, tmem + gb * 64);
                TCGEN05_LD_32X32B_X32(regs + 32, tmem + gb * 64 + 32);
                TCGEN05_WAIT_LD();
                uint32_t hw[32], lw[32];
                #pragma unroll
                for (int j = 0; j < 64; j += 2) {
                    int col = gb * 64 + j;
                    float2 bb = *reinterpret_cast<const float2*>(bias + col);
                    float v0 = apply_act(__uint_as_float(regs[j])     + bb.x, ACT);
                    float v1 = apply_act(__uint_as_float(regs[j + 1]) + bb.y, ACT);
                    split_pair_fast(v0, v1, hw[j >> 1], lw[j >> 1]);
                }
                TCGEN05_ST_32X32B_X32(A_TM + gb * 32 + woff, hw);
                TCGEN05_ST_32X32B_X32(A_TM + 128 + gb * 32 + woff, lw);
            }
            TCGEN05_WAIT_ST();
        } else {
            // L4 gemv: 8 warps, column split; cg=1 stores partial, cg=0 combines
            const int rlocal = (wid & 3) * 32 + lane;
            const int row = row0 + rlocal;
            const bool valid = (row < M);
            float gsum = 0.0f;
            #pragma unroll 1
            for (int b = 0; b < 2; b++) {
                const int gb = cg * 2 + b;
                uint32_t regs[64];
                TCGEN05_LD_32X32B_X32(regs, tmem + gb * 64);
                TCGEN05_LD_32X32B_X32(regs + 32, tmem + gb * 64 + 32);
                TCGEN05_WAIT_LD();
                #pragma unroll
                for (int j = 0; j < 64; j += 2) {
                    int col = gb * 64 + j;
                    float2 bb = *reinterpret_cast<const float2*>(bias + col);
                    float2 pp = *reinterpret_cast<const float2*>(P3 + col);
                    float v0 = apply_act(__uint_as_float(regs[j])     + bb.x, ACT);
                    float v1 = apply_act(__uint_as_float(regs[j + 1]) + bb.y, ACT);
                    gsum += v0 * pp.x + v1 * pp.y;
                }
            }
            float* scr = reinterpret_cast<float*>(smem + ABUF_OFF);
            if (cg == 1) scr[rlocal] = gsum;
            __syncthreads();
            if (cg == 0 && valid) {
                out[row] = 0.0f;
                out[(size_t)M + row] = gsum + scr[rlocal] + __ldg(pb3);
            }
        }
        TCGEN05_FENCE_BEFORE();
        __syncthreads();
    }

    if (wid == 0) {
        TCGEN05_RELINQUISH_ALLOC_PERMIT();
        TCGEN05_DEALLOC(tmem, 512);
    }
#else
    // ---- fallback (non arch-specific pass only): correct, slow SIMT path
    const int tid = threadIdx.x;
    if (tid >= 128) return;
    const int row = blockIdx.x * 128 + tid;
    if (row >= M) return;
    float cur[384], nxt[256];
    for (int k = 0; k < 128; k++)
        cur[k] = __bfloat162float(a1[(size_t)row * 256 + k])
               + __bfloat162float(a1[(size_t)row * 256 + 128 + k]);
    for (int n = 0; n < 256; n++) {
        float s = 0.f;
        for (int k = 0; k < 128; k++)
            s += cur[k] * (__bfloat162float(wt1[(size_t)n * 384 + k])
                         + __bfloat162float(wt1[(size_t)n * 384 + 128 + k]));
        nxt[n] = apply_act(s + b1[n], 1);
    }
    for (int n = 0; n < 256; n++) cur[n] = nxt[n];
    for (int n = 0; n < 256; n++) {
        float s = 0.f;
        for (int k = 0; k < 256; k++)
            s += cur[k] * (__bfloat162float(wt2[(size_t)n * 768 + k])
                         + __bfloat162float(wt2[(size_t)n * 768 + 256 + k]));
        nxt[n] = apply_act(s + b2[n], 2);
    }
    for (int n = 0; n < 256; n++) cur[n] = nxt[n];
    for (int k = 0; k < 128; k++)
        cur[256 + k] = __bfloat162float(xs[(size_t)row * 256 + k])
                     + __bfloat162float(xs[(size_t)row * 256 + 128 + k]);
    for (int n = 0; n < 256; n++) {
        float s = 0.f;
        for (int k = 0; k < 384; k++)
            s += cur[k] * (__bfloat162float(wt3[(size_t)n * 1152 + k])
                         + __bfloat162float(wt3[(size_t)n * 1152 + 384 + k]));
        nxt[n] = apply_act(s + pb1[n], 3);
    }
    for (int n = 0; n < 256; n++) cur[n] = nxt[n];
    float gsum = 0.f;
    for (int n = 0; n < 256; n++) {
        float s = 0.f;
        for (int k = 0; k < 256; k++)
            s += cur[k] * (__bfloat162float(wt4[(size_t)n * 768 + k])
                         + __bfloat162float(wt4[(size_t)n * 768 + 256 + k]));
        gsum += apply_act(s + pb2[n], 3) * P3[n];
    }
    out[row] = 0.0f;
    out[(size_t)M + row] = gsum + pb3[0];
#endif
}

// ---------------------------------------------------------------------------
// host: tensormap encoding via runtime-queried driver entry point (no -lcuda)
// ---------------------------------------------------------------------------
typedef CUresult (*EncodeTiledFn)(
    CUtensorMap*, CUtensorMapDataType, cuuint32_t, void*,
    const cuuint64_t*, const cuuint64_t*, const cuuint32_t*, const cuuint32_t*,
    CUtensorMapInterleave, CUtensorMapSwizzle, CUtensorMapL2promotion,
    CUtensorMapFloatOOBfill);

static EncodeTiledFn get_encoder()
{
    void* fn = nullptr;
    cudaDriverEntryPointQueryResult qr;
    cudaGetDriverEntryPointByVersion("cuTensorMapEncodeTiled", &fn, 12000,
                                     cudaEnableDefault, &qr);
    return (EncodeTiledFn)fn;
}

static void make_map(EncodeTiledFn enc, CUtensorMap* m, void* base,
                     uint64_t inner, uint64_t outer, uint32_t box0, uint32_t box1)
{
    cuuint64_t dims[2]    = {(cuuint64_t)inner, (cuuint64_t)outer};
    cuuint64_t strides[1] = {(cuuint64_t)(inner * 2)};
    cuuint32_t box[2]     = {(cuuint32_t)box0, (cuuint32_t)box1};
    cuuint32_t es[2]      = {1, 1};
    enc(m, CU_TENSOR_MAP_DATA_TYPE_BFLOAT16, 2, base, dims, strides, box, es,
        CU_TENSOR_MAP_INTERLEAVE_NONE, CU_TENSOR_MAP_SWIZZLE_128B,
        CU_TENSOR_MAP_L2_PROMOTION_L2_128B, CU_TENSOR_MAP_FLOAT_OOB_FILL_NONE);
}

// ---------------------------------------------------------------------------
extern "C" void kernel_launch(void* const* d_in, const int* in_sizes, int n_in,
                              void* d_out, int out_size)
{
    const float* x   = (const float*)d_in[0];
    const float* t   = (const float*)d_in[1];
    const int*   ei  = (const int*)d_in[3];
    const float* W1  = (const float*)d_in[4];
    const float* b1  = (const float*)d_in[5];
    const float* W2  = (const float*)d_in[6];
    const float* b2  = (const float*)d_in[7];
    const float* P1  = (const float*)d_in[8];
    const float* pb1 = (const float*)d_in[9];
    const float* P2  = (const float*)d_in[10];
    const float* pb2 = (const float*)d_in[11];
    const float* P3  = (const float*)d_in[12];
    const float* pb3 = (const float*)d_in[13];
    float* out = (float*)d_out;

    const int M = in_sizes[1];
    const int E = in_sizes[3] / 2;

    float *xin, *agg;
    int *cnt, *eidx;
    __nv_bfloat16 *a1, *xs, *wt1, *wt2, *wt3, *wt4;
    cudaGetSymbolAddress((void**)&xin, g_xin);
    cudaGetSymbolAddress((void**)&agg, g_agg);
    cudaGetSymbolAddress((void**)&cnt, g_cnt);
    cudaGetSymbolAddress((void**)&eidx, g_eidx);
    cudaGetSymbolAddress((void**)&a1,  g_a1);
    cudaGetSymbolAddress((void**)&xs,  g_xs);
    cudaGetSymbolAddress((void**)&wt1, g_wt1);
    cudaGetSymbolAddress((void**)&wt2, g_wt2);
    cudaGetSymbolAddress((void**)&wt3, g_wt3);
    cudaGetSymbolAddress((void**)&wt4, g_wt4);

    EncodeTiledFn enc = get_encoder();
    CUtensorMap mA1, mXS, mB1, mB2, mB3, mB4;
    make_map(enc, &mA1, a1, 256, (uint64_t)M, 64, 128);
    make_map(enc, &mXS, xs, 256, (uint64_t)M, 64, 128);
    make_map(enc, &mB1, wt1, 384,  256, 64, 256);
    make_map(enc, &mB2, wt2, 768,  256, 64, 256);
    make_map(enc, &mB3, wt3, 1152, 256, 64, 256);
    make_map(enc, &mB4, wt4, 768,  256, 64, 256);

    cudaFuncSetAttribute(fused_mlp,
                         cudaFuncAttributeMaxDynamicSharedMemorySize, SMEM_BYTES);

    // 1: build x_in, xs split; zero agg + cnt
    {
        int total = M * INCH;
        build_xin_kernel<<<(total + 255) / 256, 256>>>(x, t, xin, agg, xs, cnt, M);
    }
    // 2: bucket fill
    fill_kernel<<<(E + 255) / 256, 256>>>(ei, ei + E, xin, agg, cnt, eidx, E);
    // 3: pull aggregation -> a1 split ; weight prep appended
    {
        int pullBlocks = (M * 32 + 255) / 256;
        int prepBlocks = (HID * (384 + 768 + 1152 + 768) + 255) / 256;
        pull_prep_kernel<<<pullBlocks + prepBlocks, 256>>>(
            xin, agg, cnt, eidx, a1,
            W1, W2, P1, P2, wt1, wt2, wt3, wt4, M, pullBlocks);
    }
    // 4: fused 4-layer MLP + gemv (fast epilogue)
    {
        int tiles = (M + 127) / 128;
        fused_mlp<<<tiles, 256, SMEM_BYTES>>>(
            mA1, mXS, mB1, mB2, mB3, mB4,
            a1, xs, wt1, wt2, wt3, wt4,
            b1, b2, pb1, pb2, P3, pb3, out, M);
    }
}